// round 17
// baseline (speedup 1.0000x reference)
#include <cuda_runtime.h>
#include <cuda_bf16.h>
#include <cstdint>

#define NNODE 128
#define NM1   127            // edges per receiver
#define NRR   (NNODE * NM1)  // 16256 directed edges
#define BB    128
#define CC    16
#define NT    (BB * NNODE)   // 16384 (b, r) tiles
#define GRID  4096           // CTAs; each processes NT/GRID = 4 tiles
#define BUFB  8192           // smem bytes per buffer (8128 data + pad)

// SW128-style smem swizzle on byte offsets: XOR bits [9:7] into [6:4].
// Conflict-free for phase-1 access (8 consecutive float4s per 128B row) and
// phase-2 access (stride-4 float4 column). Buffers are 8192B-aligned regions
// so the swizzle composes with the buffer offset.
__device__ __forceinline__ unsigned swz(unsigned byte_off) {
    return byte_off ^ ((byte_off >> 3) & 0x70u);
}

__device__ __forceinline__ uint32_t smem_u32(const void* p) {
    uint32_t a;
    asm("{ .reg .u64 t; cvta.to.shared.u64 t, %1; cvt.u32.u64 %0, t; }"
        : "=r"(a) : "l"(p));
    return a;
}

// Lightly-persistent kernel: 4096 CTAs x 4 tiles, double-buffered cp.async
// prefetch (plain .cg encoding — the cache-policy variant trapped on sm_103a).
// Per tile (b = tile>>7, r = tile&127):
//   prefetch(next): 4x cp.async.cg 16B/thread, global -> swizzled smem.
//   exp phase:      4 conflict-free LDS.128 in scrambled order (f = t+128j,
//                   channel-quad q = t&3 constant), __expf, accumulate.
//   reduce:         3-stage xor-shuffle (masks 4,8,16), 4-warp smem combine,
//                   16 threads compute one __frcp_rn per channel.
//   phase 2:        thread t = edge t; 4 conflict-free LDS.128, scale,
//                   16 warp-coalesced __stcs (128B runs per channel).
__global__ __launch_bounds__(128, 12) void attention2_denom_kernel(
    const float* __restrict__ x, float* __restrict__ out)
{
    const int t    = threadIdx.x;
    const int warp = t >> 5;
    const int lane = t & 31;

    __shared__ __align__(16) unsigned char buf[2][BUFB];
    __shared__ float4 ws4[4][4];
    __shared__ float4 rden4[4];

    const uint32_t buf_base = smem_u32(buf);

    // Prefetch a tile's 508 float4s into buffer pb via cp.async (no registers).
    auto prefetch = [&](int tile, int pb) {
        const int b = tile >> 7;
        const int r = tile & (NNODE - 1);
        const float4* src = reinterpret_cast<const float4*>(
            x + ((size_t)b * NRR + (size_t)r * NM1) * CC);
        #pragma unroll
        for (int j = 0; j < 4; j++) {
            int f = t + 128 * j;
            if (f < NM1 * 4) {
                uint32_t dst = buf_base + pb * BUFB + swz(16u * (unsigned)f);
                asm volatile(
                    "cp.async.cg.shared.global [%0], [%1], 16;"
                    :: "r"(dst), "l"(src + f) : "memory");
            }
        }
        asm volatile("cp.async.commit_group;" ::: "memory");
    };

    int tile = blockIdx.x;
    prefetch(tile, 0);
    int pb = 0;

    #pragma unroll 1
    for (; tile < NT; tile += GRID) {
        // Wait for this tile's data; barrier makes it CTA-visible and also
        // fences the previous iteration's phase-2 reads of buffer pb^1.
        asm volatile("cp.async.wait_group 0;" ::: "memory");
        __syncthreads();

        const int nxt = tile + GRID;          // uniform predicate across CTA
        if (nxt < NT) prefetch(nxt, pb ^ 1);  // overlap with all work below

        const unsigned char* base = buf[pb];

        // ---- exp + accumulate (scrambled order, quad q = t&3 constant) ----
        float4 acc = make_float4(0.f, 0.f, 0.f, 0.f);
        #pragma unroll
        for (int j = 0; j < 4; j++) {
            int f = t + 128 * j;
            if (f < NM1 * 4) {
                float4 g = *reinterpret_cast<const float4*>(base + swz(16u * (unsigned)f));
                acc.x += __expf(g.x);
                acc.y += __expf(g.y);
                acc.z += __expf(g.z);
                acc.w += __expf(g.w);
            }
        }

        // ---- reduce over edges: lanes with equal quad (masks 4,8,16) ------
        #pragma unroll
        for (int m = 4; m <= 16; m <<= 1) {
            acc.x += __shfl_xor_sync(0xffffffffu, acc.x, m);
            acc.y += __shfl_xor_sync(0xffffffffu, acc.y, m);
            acc.z += __shfl_xor_sync(0xffffffffu, acc.z, m);
            acc.w += __shfl_xor_sync(0xffffffffu, acc.w, m);
        }
        if (lane < 4) ws4[warp][lane] = acc;  // lane == its quad q
        __syncthreads();

        if (t < CC) {
            const float* wsf = reinterpret_cast<const float*>(ws4);
            float d = wsf[0 * CC + t] + wsf[1 * CC + t]
                    + wsf[2 * CC + t] + wsf[3 * CC + t];
            reinterpret_cast<float*>(rden4)[t] = __frcp_rn(d);
        }
        __syncthreads();

        // ---- phase 2: edge-owned readback + coalesced streaming stores ----
        if (t < NM1) {
            const int b = tile >> 7;
            const int r = tile & (NNODE - 1);

            float4 rd0 = rden4[0], rd1 = rden4[1];
            float4 rd2 = rden4[2], rd3 = rden4[3];
            float4 v0 = *reinterpret_cast<const float4*>(base + swz(16u * (4u * t + 0)));
            float4 v1 = *reinterpret_cast<const float4*>(base + swz(16u * (4u * t + 1)));
            float4 v2 = *reinterpret_cast<const float4*>(base + swz(16u * (4u * t + 2)));
            float4 v3 = *reinterpret_cast<const float4*>(base + swz(16u * (4u * t + 3)));

            float* o = out + (size_t)b * CC * NRR + (size_t)r * NM1 + (size_t)t;
            __stcs(o +  0 * NRR, v0.x * rd0.x);  __stcs(o +  1 * NRR, v0.y * rd0.y);
            __stcs(o +  2 * NRR, v0.z * rd0.z);  __stcs(o +  3 * NRR, v0.w * rd0.w);
            __stcs(o +  4 * NRR, v1.x * rd1.x);  __stcs(o +  5 * NRR, v1.y * rd1.y);
            __stcs(o +  6 * NRR, v1.z * rd1.z);  __stcs(o +  7 * NRR, v1.w * rd1.w);
            __stcs(o +  8 * NRR, v2.x * rd2.x);  __stcs(o +  9 * NRR, v2.y * rd2.y);
            __stcs(o + 10 * NRR, v2.z * rd2.z);  __stcs(o + 11 * NRR, v2.w * rd2.w);
            __stcs(o + 12 * NRR, v3.x * rd3.x);  __stcs(o + 13 * NRR, v3.y * rd3.y);
            __stcs(o + 14 * NRR, v3.z * rd3.z);  __stcs(o + 15 * NRR, v3.w * rd3.w);
        }
        pb ^= 1;
    }
}

extern "C" void kernel_launch(void* const* d_in, const int* in_sizes, int n_in,
                              void* d_out, int out_size)
{
    // d_in[0]: x  float32 [B, NR, C]
    // d_in[1]: receivers int32 [NR] — structurally i/(N-1), unused
    const float* x   = (const float*)d_in[0];
    float*       out = (float*)d_out;   // float32 [B, C, NR]

    attention2_denom_kernel<<<GRID, 128>>>(x, out);
}